// round 16
// baseline (speedup 1.0000x reference)
#include <cuda_runtime.h>
#include <cuda_bf16.h>
#include <cstdint>

#define NSTR   4
#define T_LEN  8192
#define D_HID  2048
#define ND     8192
#define NOUT   24
#define NACC   25
#define KC     64
#define NSLOT  8                 // 4 segments x 2 k-halves
#define NT2    16                // tiles per CTA (k = 1024)
#define WELEM  1728              // 24 rows * 72 bf16 per packed W tile
#define WB     3456              // bytes per packed W tile
#define NBS    6                 // B ring slots

// smem layout (bytes from 1024-aligned base tb)
#define A_SLOT    16384          // bf16 A tile: 128 rows x 128B (SW128), x2
#define B_OFF     32768          // 6 x 3456 B ring
#define SMEM_DYN  (1024 + 32768 + NBS * WB)   // 54,528 -> 4 CTAs/SM

// packed bf16 weights: [s*32 + tile][24 rows][72 (64 data + 8 pad)]
__device__ __align__(16) __nv_bfloat16 g_w[NSTR * 32 * WELEM];
// partials: [slot][acc][row]
__device__ float g_scratch[NSLOT][NACC][T_LEN];
// per-rowblock arrival counters (reset to 0 by consumer -> replay-safe)
__device__ int g_cnt[64];

__device__ __forceinline__ uint32_t sw128(uint32_t o) {
    return o ^ ((o >> 3) & 0x70u);
}
__device__ __forceinline__ uint32_t cvt2(float lo, float hi) {
    uint32_t r;
    asm("cvt.rn.bf16x2.f32 %0, %1, %2;" : "=r"(r) : "f"(hi), "f"(lo));
    return r;
}
__device__ __forceinline__ void sts64(uint32_t a, uint32_t x, uint32_t y) {
    asm volatile("st.shared.v2.b32 [%0], {%1, %2};" :: "r"(a), "r"(x), "r"(y) : "memory");
}
__device__ __forceinline__ uint32_t lds32(uint32_t a) {
    uint32_t v;
    asm volatile("ld.shared.b32 %0, [%1];" : "=r"(v) : "r"(a));
    return v;
}
__device__ __forceinline__ void cp16(uint32_t dst, const void* src) {
    asm volatile("cp.async.cg.shared.global [%0], [%1], 16;" :: "r"(dst), "l"(src) : "memory");
}
__device__ __forceinline__ void cp_commit() {
    asm volatile("cp.async.commit_group;" ::: "memory");
}
template <int N> __device__ __forceinline__ void cp_wait() {
    asm volatile("cp.async.wait_group %0;" :: "n"(N) : "memory");
}
__device__ __forceinline__ void ldsm4(uint32_t* r, uint32_t addr) {
    asm volatile("ldmatrix.sync.aligned.m8n8.x4.shared.b16 {%0,%1,%2,%3}, [%4];"
                 : "=r"(r[0]), "=r"(r[1]), "=r"(r[2]), "=r"(r[3]) : "r"(addr));
}
__device__ __forceinline__ void mma4(float* d, const uint32_t* a,
                                     uint32_t b0, uint32_t b1) {
    asm volatile(
        "mma.sync.aligned.m16n8k16.row.col.f32.bf16.bf16.f32 "
        "{%0,%1,%2,%3}, {%4,%5,%6,%7}, {%8,%9}, {%0,%1,%2,%3};"
        : "+f"(d[0]), "+f"(d[1]), "+f"(d[2]), "+f"(d[3])
        : "r"(a[0]), "r"(a[1]), "r"(a[2]), "r"(a[3]), "r"(b0), "r"(b1));
}

// ---- W pack (vectorized): bf16, [24][72] rows per (s,tile) ----
__global__ void mhc_prep(const float* __restrict__ Wpre,
                         const float* __restrict__ Wpost,
                         const float* __restrict__ Wres)
{
    const int id  = blockIdx.x * 256 + threadIdx.x;   // 0..49151
    const int k4  = id & 15;
    const int j   = (id >> 4) % 24;
    const int st  = (id >> 4) / 24;                   // s*32 + tile
    const int s   = st >> 5, tile = st & 31;

    const int kg = s * D_HID + tile * KC + k4 * 4;
    const float* src;
    if (j < 4)      src = Wpre  + (size_t)j       * ND + kg;
    else if (j < 8) src = Wpost + (size_t)(j - 4) * ND + kg;
    else            src = Wres  + (size_t)(j - 8) * ND + kg;
    const float4 v = *reinterpret_cast<const float4*>(src);

    uint2 o;
    o.x = cvt2(v.x, v.y);
    o.y = cvt2(v.z, v.w);
    *reinterpret_cast<uint2*>(
        reinterpret_cast<unsigned char*>(g_w) +
        (size_t)st * WB + j * 144 + k4 * 8) = o;
}

extern __shared__ unsigned char dsm[];

__global__ __launch_bounds__(256, 4)
void mhc_main_mma(const float* __restrict__ stream,
                  const float* __restrict__ bpre,
                  const float* __restrict__ bpost,
                  const float* __restrict__ bres,
                  const float* __restrict__ apre_p,
                  const float* __restrict__ apost_p,
                  const float* __restrict__ ares_p,
                  float* __restrict__ out)
{
    const int tid  = threadIdx.x;
    const int w    = tid >> 5, lane = tid & 31;
    const int g    = lane >> 3, c = lane & 7;       // X-load mapping
    const int g4   = lane >> 2, t4 = lane & 3;      // mma B-frag mapping
    const int rb   = blockIdx.x & 63;
    const int s2   = blockIdx.x >> 6;               // slot 0..7
    const int s    = s2 >> 1;
    const int half = s2 & 1;
    const int R    = rb * 128;

    const uint32_t raw = (uint32_t)__cvta_generic_to_shared(dsm);
    const uint32_t tb  = (raw + 1023u) & ~1023u;
    const uint32_t bsb = tb + B_OFF;

    const float* xbase = stream + ((size_t)s * T_LEN + R) * D_HID + half * 1024;

    // per-warp A ownership: warp w owns rows w*16 .. w*16+15
    int rr[4];
#pragma unroll
    for (int p = 0; p < 4; p++) rr[p] = w * 16 + p * 4 + g;

    // ldmatrix per-thread A offset (quadrant order) — same 16 rows
    const int q    = lane >> 3;
    const int arow = w * 16 + (q & 1) * 8 + (lane & 7);
    const uint32_t aoff = (uint32_t)(arow * 128 + (q >> 1) * 16);

    // B fragment base offset (row stride 144B)
    const uint32_t boffbase = (uint32_t)(g4 * 144 + t4 * 4);

    float acc[3][4];
#pragma unroll
    for (int j = 0; j < 3; j++)
#pragma unroll
        for (int i = 0; i < 4; i++) acc[j][i] = 0.f;
    float ss[4] = {0.f, 0.f, 0.f, 0.f};

    float4 xr[4];    // half of an X tile (reused; lives across barriers)

    auto ldx = [&](int t, int h) {
#pragma unroll
        for (int pp = 0; pp < 2; pp++)
#pragma unroll
            for (int u = 0; u < 2; u++)
                xr[pp * 2 + u] = *reinterpret_cast<const float4*>(
                    xbase + (size_t)rr[2 * h + pp] * D_HID + t * KC + u * 32 + c * 4);
    };
    auto stx = [&](int b, int h) {
        const uint32_t ab = tb + (uint32_t)b * A_SLOT;
#pragma unroll
        for (int pp = 0; pp < 2; pp++) {
            const int p = 2 * h + pp;
#pragma unroll
            for (int u = 0; u < 2; u++) {
                const float4 qv = xr[pp * 2 + u];
                const uint32_t h01 = cvt2(qv.x, qv.y);
                const uint32_t h23 = cvt2(qv.z, qv.w);
                const uint32_t off = sw128((uint32_t)(rr[p] * 128 + u * 64 + c * 8));
                sts64(ab + off, h01, h23);
                ss[p] = fmaf(qv.x, qv.x, fmaf(qv.y, qv.y,
                         fmaf(qv.z, qv.z, fmaf(qv.w, qv.w, ss[p]))));
            }
        }
    };
    auto stage_b = [&](int t) {      // stage tile t into slot t%NBS (if valid)
        if (t < NT2 && tid < 216) {
            const size_t base = (size_t)(s * 32 + half * NT2 + t) * WELEM;
            cp16(bsb + (uint32_t)(t % NBS) * WB + tid * 16,
                 (const unsigned char*)g_w + base * 2 + tid * 16);
        }
        cp_commit();
    };
    auto compute_kc = [&](uint32_t ab, uint32_t bb, int kc) {
        uint32_t ah[4];
        ldsm4(ah, ab + sw128(aoff + kc * 32));
#pragma unroll
        for (int j = 0; j < 3; j++) {
            const uint32_t bo = bb + boffbase + (uint32_t)(j * 8 * 144 + kc * 32);
            mma4(acc[j], ah, lds32(bo), lds32(bo + 16));
        }
    };

    // ---- prologue: B(0..3) staged (4 groups); X tile0 in A slot0; ldx(1,0) ----
    stage_b(0); stage_b(1); stage_b(2); stage_b(3);
    ldx(0, 0); stx(0, 0);
    ldx(0, 1); stx(0, 1);
    ldx(1, 0);
    cp_wait<2>();                 // B(0), B(1) resident
    __syncthreads();

    // ---- mainloop: 2 tiles per CTA barrier; 6-slot B ring, distance 4 ----
#pragma unroll 1
    for (int t = 0; t < NT2; t += 2) {
        // ---- tile t (A slot 0) ----
        {
            const uint32_t ab = tb;
            const uint32_t bb = bsb + (uint32_t)(t % NBS) * WB;
            stage_b(t + 4);
            compute_kc(ab, bb, 0);
            compute_kc(ab, bb, 1);
            stx(1, 0); ldx(t + 1, 1);                 // fill A slot1 for t+1
            compute_kc(ab, bb, 2);
            compute_kc(ab, bb, 3);
            stx(1, 1);
            if (t + 2 < NT2) ldx(t + 2, 0);
            __syncwarp();
        }
        // ---- tile t+1 (A slot 1) ----
        {
            const uint32_t ab = tb + A_SLOT;
            const uint32_t bb = bsb + (uint32_t)((t + 1) % NBS) * WB;
            stage_b(t + 5);
            compute_kc(ab, bb, 0);
            compute_kc(ab, bb, 1);
            if (t + 2 < NT2) { stx(0, 0); ldx(t + 2, 1); }
            compute_kc(ab, bb, 2);
            compute_kc(ab, bb, 3);
            if (t + 2 < NT2) {
                stx(0, 1);
                if (t + 3 < NT2) ldx(t + 3, 0);
            }
            __syncwarp();
        }
        cp_wait<2>();             // B(t+2), B(t+3) resident; t+4/t+5 in flight
        __syncthreads();          // publish them CTA-wide
    }

    // ---- sumsq: reduce over the 8 c-lanes per row ----
#pragma unroll
    for (int p = 0; p < 4; p++) {
        float v = ss[p];
        v += __shfl_down_sync(0xffffffffu, v, 4, 8);
        v += __shfl_down_sync(0xffffffffu, v, 2, 8);
        v += __shfl_down_sync(0xffffffffu, v, 1, 8);
        if (c == 0) g_scratch[s2][24][R + rr[p]] = v;
    }

    // ---- write dot partials: warp w owns rows R + w*16 .. +15 ----
    const int row0 = R + w * 16 + g4;
#pragma unroll
    for (int j = 0; j < 3; j++) {
        const int col = j * 8 + t4 * 2;
        g_scratch[s2][col    ][row0]     = acc[j][0];
        g_scratch[s2][col + 1][row0]     = acc[j][1];
        g_scratch[s2][col    ][row0 + 8] = acc[j][2];
        g_scratch[s2][col + 1][row0 + 8] = acc[j][3];
    }

    // ---- fused epilogue: 8th arriver per rowblock finishes rows R..R+127 ----
    __shared__ int s_last;
    __threadfence();
    __syncthreads();
    if (tid == 0) s_last = (atomicAdd(&g_cnt[rb], 1) == NSLOT - 1);
    __syncthreads();
    if (!s_last) return;

    if (tid < 128) {
        const int t = R + tid;

        float v[NACC];
#pragma unroll
        for (int i = 0; i < NACC; i++) {
            float a = 0.f;
#pragma unroll
            for (int sl = 0; sl < NSLOT; sl++)
                a += __ldcg(&g_scratch[sl][i][t]);
            v[i] = a;
        }

        const float rn = rsqrtf(v[24] * (1.0f / (float)ND) + 1e-8f);
        const float apre  = *apre_p;
        const float apost = *apost_p;
        const float ares  = *ares_p;

        float* outres  = out;                          // (T,4,4)
        float* outpre  = out + (size_t)T_LEN * 16;     // (T,4)
        float* outpost = out + (size_t)T_LEN * 20;     // (T,4)

#pragma unroll
        for (int k = 0; k < 4; k++) {
            const float z = apre * v[k] * rn + bpre[k];
            outpre[(size_t)t * 4 + k] = __fdividef(1.0f, 1.0f + __expf(-z));
        }
#pragma unroll
        for (int k = 0; k < 4; k++) {
            const float z = apost * v[4 + k] * rn + bpost[k];
            outpost[(size_t)t * 4 + k] = __fdividef(2.0f, 1.0f + __expf(-z));
        }

        float M[16];
#pragma unroll
        for (int i = 0; i < 16; i++)
            M[i] = __expf(ares * v[8 + i] * rn + bres[i]);

        for (int it = 0; it < 20; it++) {
#pragma unroll
            for (int a = 0; a < 4; a++) {
                const float r = __fdividef(1.0f,
                    M[4*a] + M[4*a+1] + M[4*a+2] + M[4*a+3]);
                M[4*a] *= r; M[4*a+1] *= r; M[4*a+2] *= r; M[4*a+3] *= r;
            }
#pragma unroll
            for (int b = 0; b < 4; b++) {
                const float r = __fdividef(1.0f,
                    M[b] + M[4+b] + M[8+b] + M[12+b]);
                M[b] *= r; M[4+b] *= r; M[8+b] *= r; M[12+b] *= r;
            }
        }
#pragma unroll
        for (int i = 0; i < 16; i++) outres[(size_t)t * 16 + i] = M[i];
    }

    __syncthreads();
    if (tid == 0) g_cnt[rb] = 0;    // reset for next graph replay
}

extern "C" void kernel_launch(void* const* d_in, const int* in_sizes, int n_in,
                              void* d_out, int out_size) {
    const float* stream = (const float*)d_in[0];
    const float* Wpre   = (const float*)d_in[1];
    const float* Wpost  = (const float*)d_in[2];
    const float* Wres   = (const float*)d_in[3];
    const float* bpre   = (const float*)d_in[4];
    const float* bpost  = (const float*)d_in[5];
    const float* bres   = (const float*)d_in[6];
    const float* apre   = (const float*)d_in[7];
    const float* apost  = (const float*)d_in[8];
    const float* ares   = (const float*)d_in[9];

    cudaFuncSetAttribute(mhc_main_mma,
                         cudaFuncAttributeMaxDynamicSharedMemorySize, SMEM_DYN);

    mhc_prep<<<192, 256>>>(Wpre, Wpost, Wres);
    mhc_main_mma<<<512, 256, SMEM_DYN>>>(stream, bpre, bpost, bres,
                                         apre, apost, ares, (float*)d_out);
}

// round 17
// speedup vs baseline: 1.3258x; 1.3258x over previous
#include <cuda_runtime.h>
#include <cuda_bf16.h>
#include <cstdint>

#define NSTR   4
#define T_LEN  8192
#define D_HID  2048
#define ND     8192
#define NOUT   24
#define NACC   25
#define KC     64
#define NSLOT  8                 // 4 segments x 2 k-halves
#define NT2    16                // tiles per CTA (k = 1024)
#define WB     3072              // bytes per packed W tile (12 grp x 32 lanes x 8B)

// smem layout (bytes from 1024-aligned base tb)
#define A_SLOT    16384          // bf16 A tile: 128 rows x 128B (SW128), x2
#define B_OFF     32768          // 3 x 3072 B ring
#define SMEM_DYN  (1024 + 32768 + 3 * WB)   // 42,240 -> 4 CTAs/SM

// B packed in mma-fragment order: [s*32+tile][kc*3+j][lane] of uint2 (8B)
__device__ __align__(16) uint2 g_wf[128 * 12 * 32];   // 393 KB
// partials: [slot][acc][row]
__device__ float g_scratch[NSLOT][NACC][T_LEN];
// per-rowblock arrival counters (reset to 0 by consumer -> replay-safe)
__device__ int g_cnt[64];

__device__ __forceinline__ uint32_t sw128(uint32_t o) {
    return o ^ ((o >> 3) & 0x70u);
}
__device__ __forceinline__ uint32_t cvt2(float lo, float hi) {
    uint32_t r;
    asm("cvt.rn.bf16x2.f32 %0, %1, %2;" : "=r"(r) : "f"(hi), "f"(lo));
    return r;
}
__device__ __forceinline__ void sts64(uint32_t a, uint32_t x, uint32_t y) {
    asm volatile("st.shared.v2.b32 [%0], {%1, %2};" :: "r"(a), "r"(x), "r"(y) : "memory");
}
__device__ __forceinline__ uint2 lds64(uint32_t a) {
    uint2 v;
    asm volatile("ld.shared.v2.u32 {%0,%1}, [%2];" : "=r"(v.x), "=r"(v.y) : "r"(a));
    return v;
}
__device__ __forceinline__ void cp16(uint32_t dst, const void* src) {
    asm volatile("cp.async.cg.shared.global [%0], [%1], 16;" :: "r"(dst), "l"(src) : "memory");
}
__device__ __forceinline__ void cp_commit() {
    asm volatile("cp.async.commit_group;" ::: "memory");
}
template <int N> __device__ __forceinline__ void cp_wait() {
    asm volatile("cp.async.wait_group %0;" :: "n"(N) : "memory");
}
__device__ __forceinline__ void ldsm4(uint32_t* r, uint32_t addr) {
    asm volatile("ldmatrix.sync.aligned.m8n8.x4.shared.b16 {%0,%1,%2,%3}, [%4];"
                 : "=r"(r[0]), "=r"(r[1]), "=r"(r[2]), "=r"(r[3]) : "r"(addr));
}
__device__ __forceinline__ void mma4(float* d, const uint32_t* a,
                                     uint32_t b0, uint32_t b1) {
    asm volatile(
        "mma.sync.aligned.m16n8k16.row.col.f32.bf16.bf16.f32 "
        "{%0,%1,%2,%3}, {%4,%5,%6,%7}, {%8,%9}, {%0,%1,%2,%3};"
        : "+f"(d[0]), "+f"(d[1]), "+f"(d[2]), "+f"(d[3])
        : "r"(a[0]), "r"(a[1]), "r"(a[2]), "r"(a[3]), "r"(b0), "r"(b1));
}

// ---- W pack into mma B-fragment order ----
// unit (st, grp=kc*3+j, lane): lane (g4=lane>>2, t4=lane&3) holds
//   b0 = {W[n][k0], W[n][k0+1]},  b1 = {W[n][k0+8], W[n][k0+9]}
// with n = j*8+g4, k0 = s*2048 + tile*64 + kc*16 + t4*2
__global__ void mhc_prep(const float* __restrict__ Wpre,
                         const float* __restrict__ Wpost,
                         const float* __restrict__ Wres)
{
    const int id   = blockIdx.x * 256 + threadIdx.x;   // 0..49151
    const int lane = id & 31;
    const int grp  = (id >> 5) % 12;
    const int st   = id / 384;                         // s*32 + tile
    const int kc = grp / 3, j = grp % 3;
    const int g4 = lane >> 2, t4 = lane & 3;
    const int n  = j * 8 + g4;
    const int s  = st >> 5, tile = st & 31;
    const int k0 = s * D_HID + tile * KC + kc * 16 + t4 * 2;

    const float* src;
    if (n < 4)      src = Wpre  + (size_t)n       * ND;
    else if (n < 8) src = Wpost + (size_t)(n - 4) * ND;
    else            src = Wres  + (size_t)(n - 8) * ND;

    const float2 a = *reinterpret_cast<const float2*>(src + k0);
    const float2 b = *reinterpret_cast<const float2*>(src + k0 + 8);
    uint2 o;
    o.x = cvt2(a.x, a.y);
    o.y = cvt2(b.x, b.y);
    g_wf[id] = o;
}

extern __shared__ unsigned char dsm[];

__global__ __launch_bounds__(256, 4)
void mhc_main_mma(const float* __restrict__ stream,
                  const float* __restrict__ bpre,
                  const float* __restrict__ bpost,
                  const float* __restrict__ bres,
                  const float* __restrict__ apre_p,
                  const float* __restrict__ apost_p,
                  const float* __restrict__ ares_p,
                  float* __restrict__ out)
{
    const int tid  = threadIdx.x;
    const int w    = tid >> 5, lane = tid & 31;
    const int g    = lane >> 3, c = lane & 7;       // X-load mapping
    const int g4   = lane >> 2, t4 = lane & 3;      // mma B-frag mapping
    const int rb   = blockIdx.x & 63;
    const int s2   = blockIdx.x >> 6;               // slot 0..7
    const int s    = s2 >> 1;
    const int half = s2 & 1;
    const int R    = rb * 128;

    const uint32_t raw = (uint32_t)__cvta_generic_to_shared(dsm);
    const uint32_t tb  = (raw + 1023u) & ~1023u;
    const uint32_t bsb = tb + B_OFF;

    const float* xbase = stream + ((size_t)s * T_LEN + R) * D_HID + half * 1024;

    // per-warp A ownership: warp w owns rows w*16 .. w*16+15
    int rr[4];
#pragma unroll
    for (int p = 0; p < 4; p++) rr[p] = w * 16 + p * 4 + g;

    // ldmatrix per-thread A offset (quadrant order) — same 16 rows
    const int q    = lane >> 3;
    const int arow = w * 16 + (q & 1) * 8 + (lane & 7);
    const uint32_t aoff = (uint32_t)(arow * 128 + (q >> 1) * 16);

    float acc[3][4];
#pragma unroll
    for (int j = 0; j < 3; j++)
#pragma unroll
        for (int i = 0; i < 4; i++) acc[j][i] = 0.f;
    float ss[4] = {0.f, 0.f, 0.f, 0.f};

    float4 xr[4];    // half of an X tile (reused; lives across barriers)

    auto ldx = [&](int t, int h) {
#pragma unroll
        for (int pp = 0; pp < 2; pp++)
#pragma unroll
            for (int u = 0; u < 2; u++)
                xr[pp * 2 + u] = *reinterpret_cast<const float4*>(
                    xbase + (size_t)rr[2 * h + pp] * D_HID + t * KC + u * 32 + c * 4);
    };
    auto stx = [&](int b, int h) {
        const uint32_t ab = tb + (uint32_t)b * A_SLOT;
#pragma unroll
        for (int pp = 0; pp < 2; pp++) {
            const int p = 2 * h + pp;
#pragma unroll
            for (int u = 0; u < 2; u++) {
                const float4 qv = xr[pp * 2 + u];
                const uint32_t h01 = cvt2(qv.x, qv.y);
                const uint32_t h23 = cvt2(qv.z, qv.w);
                const uint32_t off = sw128((uint32_t)(rr[p] * 128 + u * 64 + c * 8));
                sts64(ab + off, h01, h23);
                ss[p] = fmaf(qv.x, qv.x, fmaf(qv.y, qv.y,
                         fmaf(qv.z, qv.z, fmaf(qv.w, qv.w, ss[p]))));
            }
        }
    };
    auto stage_b = [&](int t, int slot) {
        if (tid < 192) {
            const size_t base = (size_t)(s * 32 + half * NT2 + t) * WB;
            cp16(bsb + (uint32_t)slot * WB + tid * 16,
                 (const unsigned char*)g_wf + base + tid * 16);
        }
    };
    auto compute_kc = [&](uint32_t ab, uint32_t bb, int kc) {
        uint32_t ah[4];
        ldsm4(ah, ab + sw128(aoff + kc * 32));
#pragma unroll
        for (int j = 0; j < 3; j++) {
            const uint2 bv = lds64(bb + (uint32_t)((kc * 3 + j) * 256) + lane * 8);
            mma4(acc[j], ah, bv.x, bv.y);
        }
    };

    // ---- prologue ----
    stage_b(0, 0); cp_commit();
    stage_b(1, 1); cp_commit();
    ldx(0, 0); stx(0, 0);
    ldx(0, 1); stx(0, 1);
    ldx(1, 0);
    cp_wait<1>();                 // B(0) resident
    __syncthreads();

    // ---- mainloop: 3-slot B ring (distance 2), rotated X prefetch ----
    for (int t = 0; t < NT2; ++t) {
        const int b  = t & 1;
        const uint32_t ab = tb + (uint32_t)b * A_SLOT;
        const uint32_t bb = bsb + (uint32_t)(t % 3) * WB;
        const bool pre = (t + 1 < NT2);

        if (t + 2 < NT2) stage_b(t + 2, (t + 2) % 3);
        cp_commit();

        compute_kc(ab, bb, 0);
        compute_kc(ab, bb, 1);
        if (pre) { stx(b ^ 1, 0); ldx(t + 1, 1); }
        compute_kc(ab, bb, 2);
        compute_kc(ab, bb, 3);
        if (pre) {
            stx(b ^ 1, 1);
            if (t + 2 < NT2) ldx(t + 2, 0);
        }

        cp_wait<1>();             // B(t+1) resident
        __syncthreads();
    }

    // ---- sumsq: reduce over the 8 c-lanes per row ----
#pragma unroll
    for (int p = 0; p < 4; p++) {
        float v = ss[p];
        v += __shfl_down_sync(0xffffffffu, v, 4, 8);
        v += __shfl_down_sync(0xffffffffu, v, 2, 8);
        v += __shfl_down_sync(0xffffffffu, v, 1, 8);
        if (c == 0) g_scratch[s2][24][R + rr[p]] = v;
    }

    // ---- write dot partials: warp w owns rows R + w*16 .. +15 ----
    const int row0 = R + w * 16 + g4;
#pragma unroll
    for (int j = 0; j < 3; j++) {
        const int col = j * 8 + t4 * 2;
        g_scratch[s2][col    ][row0]     = acc[j][0];
        g_scratch[s2][col + 1][row0]     = acc[j][1];
        g_scratch[s2][col    ][row0 + 8] = acc[j][2];
        g_scratch[s2][col + 1][row0 + 8] = acc[j][3];
    }

    // ---- fused epilogue: 8th arriver per rowblock finishes rows R..R+127 ----
    __shared__ int s_last;
    __threadfence();
    __syncthreads();
    if (tid == 0) s_last = (atomicAdd(&g_cnt[rb], 1) == NSLOT - 1);
    __syncthreads();
    if (!s_last) return;

    if (tid < 128) {
        const int t = R + tid;

        float v[NACC];
#pragma unroll
        for (int i = 0; i < NACC; i++) {
            float a = 0.f;
#pragma unroll
            for (int sl = 0; sl < NSLOT; sl++)
                a += __ldcg(&g_scratch[sl][i][t]);
            v[i] = a;
        }

        const float rn = rsqrtf(v[24] * (1.0f / (float)ND) + 1e-8f);
        const float apre  = *apre_p;
        const float apost = *apost_p;
        const float ares  = *ares_p;

        float* outres  = out;                          // (T,4,4)
        float* outpre  = out + (size_t)T_LEN * 16;     // (T,4)
        float* outpost = out + (size_t)T_LEN * 20;     // (T,4)

#pragma unroll
        for (int k = 0; k < 4; k++) {
            const float z = apre * v[k] * rn + bpre[k];
            outpre[(size_t)t * 4 + k] = __fdividef(1.0f, 1.0f + __expf(-z));
        }
#pragma unroll
        for (int k = 0; k < 4; k++) {
            const float z = apost * v[4 + k] * rn + bpost[k];
            outpost[(size_t)t * 4 + k] = __fdividef(2.0f, 1.0f + __expf(-z));
        }

        float M[16];
#pragma unroll
        for (int i = 0; i < 16; i++)
            M[i] = __expf(ares * v[8 + i] * rn + bres[i]);

        for (int it = 0; it < 20; it++) {
#pragma unroll
            for (int a = 0; a < 4; a++) {
                const float r = __fdividef(1.0f,
                    M[4*a] + M[4*a+1] + M[4*a+2] + M[4*a+3]);
                M[4*a] *= r; M[4*a+1] *= r; M[4*a+2] *= r; M[4*a+3] *= r;
            }
#pragma unroll
            for (int b = 0; b < 4; b++) {
                const float r = __fdividef(1.0f,
                    M[b] + M[4+b] + M[8+b] + M[12+b]);
                M[b] *= r; M[4+b] *= r; M[8+b] *= r; M[12+b] *= r;
            }
        }
#pragma unroll
        for (int i = 0; i < 16; i++) outres[(size_t)t * 16 + i] = M[i];
    }

    __syncthreads();
    if (tid == 0) g_cnt[rb] = 0;    // reset for next graph replay
}

extern "C" void kernel_launch(void* const* d_in, const int* in_sizes, int n_in,
                              void* d_out, int out_size) {
    const float* stream = (const float*)d_in[0];
    const float* Wpre   = (const float*)d_in[1];
    const float* Wpost  = (const float*)d_in[2];
    const float* Wres   = (const float*)d_in[3];
    const float* bpre   = (const float*)d_in[4];
    const float* bpost  = (const float*)d_in[5];
    const float* bres   = (const float*)d_in[6];
    const float* apre   = (const float*)d_in[7];
    const float* apost  = (const float*)d_in[8];
    const float* ares   = (const float*)d_in[9];

    cudaFuncSetAttribute(mhc_main_mma,
                         cudaFuncAttributeMaxDynamicSharedMemorySize, SMEM_DYN);

    mhc_prep<<<192, 256>>>(Wpre, Wpost, Wres);
    mhc_main_mma<<<512, 256, SMEM_DYN>>>(stream, bpre, bpost, bres,
                                         apre, apost, ares, (float*)d_out);
}